// round 5
// baseline (speedup 1.0000x reference)
#include <cuda_runtime.h>
#include <math.h>

#define TB   8
#define TD   512
#define TDD  1024
#define TT   4096
#define NCTA 128
#define CJ   8        // h cols per CTA
#define CI   4        // p cols per CTA
#define NTHR 512
#define NWARP 16

__device__ float gMem[TB * TD];              // recurrent state
__device__ float gH[TB * TDD];               // hidden activations
__device__ float gXp[TT * TB * TDD];         // precomputed x @ W1x^T  [t][b][j]
__device__ __align__(256) unsigned gBarH[64];
__device__ __align__(256) unsigned gBarM[64];

__global__ void init_scratch() {
    int t = blockIdx.x * blockDim.x + threadIdx.x;
    if (t < TB * TD) gMem[t] = 0.0f;
    if (t < 64) { gBarH[t] = 0u; gBarM[t] = 0u; }
}

__device__ __forceinline__ void fma2(unsigned long long& acc,
                                     unsigned long long a,
                                     unsigned long long b) {
    asm volatile("fma.rn.f32x2 %0, %1, %2, %0;" : "+l"(acc) : "l"(a), "l"(b));
}
__device__ __forceinline__ float2 u2f(unsigned long long v) {
    float2 f;
    asm("mov.b64 {%0,%1}, %2;" : "=f"(f.x), "=f"(f.y) : "l"(v));
    return f;
}
__device__ __forceinline__ unsigned long long fdup(float v) {
    unsigned long long r;
    asm("mov.b64 %0, {%1,%1};" : "=l"(r) : "f"(v));
    return r;
}
__device__ __forceinline__ ulonglong2 ldg128_cg(const void* p) {
    ulonglong2 v;
    asm volatile("ld.global.cg.v2.u64 {%0,%1}, [%2];"
                 : "=l"(v.x), "=l"(v.y) : "l"(p));
    return v;
}
__device__ __forceinline__ void stg_cg(float* p, float v) {
    asm volatile("st.global.cg.f32 [%0], %1;" :: "l"(p), "f"(v) : "memory");
}
__device__ __forceinline__ void bar_arrive(unsigned* ctr) {
    unsigned one = 1u;
    asm volatile("red.release.gpu.global.add.u32 [%0], %1;"
                 :: "l"(ctr), "r"(one) : "memory");
}
__device__ __forceinline__ void bar_spin(const unsigned* ctr, unsigned tgt) {
    unsigned v;
    do {
        asm volatile("ld.relaxed.gpu.global.u32 %0, [%1];"
                     : "=r"(v) : "l"(ctr) : "memory");
    } while (v < tgt);
}

// ======================= xproj precompute GEMM =============================
// gXp[t][b][j] = sum_{k<512} x[b][t][k] * W1[j][k]
// M = 32768 rows (r = b*4096+t), N = 1024, K = 512.
#define PM 128
#define PN 64
#define PK 32

__global__ void __launch_bounds__(256, 3)
xproj_kernel(const float* __restrict__ x, const float* __restrict__ W1) {
    __shared__ float As[PK][PM];                   // 16 KB, [k][m]
    __shared__ unsigned long long Bs[PK][PN];      // 16 KB, dup pairs [k][n]

    const int tid = threadIdx.x;
    const int n0 = blockIdx.x * PN;                // 16 n-tiles (fastest -> L2 A reuse)
    const int m0 = blockIdx.y * PM;                // 256 m-tiles
    const int tx = tid & 15;                       // n-group: n = tx*4..+3
    const int ty = tid >> 4;                       // m-group: m = ty*8..+7

    unsigned long long acc[4][4];
#pragma unroll
    for (int a = 0; a < 4; ++a)
#pragma unroll
        for (int c = 0; c < 4; ++c) acc[a][c] = 0ull;

    for (int kt = 0; kt < 512; kt += PK) {
        __syncthreads();
        {   // A: 128 rows x 32 k
            const int m = tid & 127, kh = tid >> 7;        // kh 0/1 -> 16 k each
            const float* src = x + (size_t)(m0 + m) * 512 + kt + kh * 16;
#pragma unroll
            for (int q = 0; q < 4; ++q) {
                float4 v = *(const float4*)(src + q * 4);
                const int kk = kh * 16 + q * 4;
                As[kk + 0][m] = v.x; As[kk + 1][m] = v.y;
                As[kk + 2][m] = v.z; As[kk + 3][m] = v.w;
            }
        }
        {   // B: 64 rows x 32 k, duplicated pairs
            const int n = tid & 63, kh = tid >> 6;         // kh 0..3 -> 8 k each
            const float* src = W1 + (size_t)(n0 + n) * 1024 + kt + kh * 8;
#pragma unroll
            for (int q = 0; q < 2; ++q) {
                float4 v = *(const float4*)(src + q * 4);
                const int kk = kh * 8 + q * 4;
                Bs[kk + 0][n] = fdup(v.x); Bs[kk + 1][n] = fdup(v.y);
                Bs[kk + 2][n] = fdup(v.z); Bs[kk + 3][n] = fdup(v.w);
            }
        }
        __syncthreads();
#pragma unroll
        for (int k = 0; k < PK; ++k) {
            const ulonglong2 a01 = *(const ulonglong2*)&As[k][ty * 8];
            const ulonglong2 a23 = *(const ulonglong2*)&As[k][ty * 8 + 4];
            const ulonglong2 b01 = *(const ulonglong2*)&Bs[k][tx * 4];
            const ulonglong2 b23 = *(const ulonglong2*)&Bs[k][tx * 4 + 2];
            fma2(acc[0][0], a01.x, b01.x); fma2(acc[0][1], a01.x, b01.y);
            fma2(acc[0][2], a01.x, b23.x); fma2(acc[0][3], a01.x, b23.y);
            fma2(acc[1][0], a01.y, b01.x); fma2(acc[1][1], a01.y, b01.y);
            fma2(acc[1][2], a01.y, b23.x); fma2(acc[1][3], a01.y, b23.y);
            fma2(acc[2][0], a23.x, b01.x); fma2(acc[2][1], a23.x, b01.y);
            fma2(acc[2][2], a23.x, b23.x); fma2(acc[2][3], a23.x, b23.y);
            fma2(acc[3][0], a23.y, b01.x); fma2(acc[3][1], a23.y, b01.y);
            fma2(acc[3][2], a23.y, b23.x); fma2(acc[3][3], a23.y, b23.y);
        }
    }
    // store: acc[mp][n] holds (m_even, m_odd) for column n0+tx*4+n
#pragma unroll
    for (int mp = 0; mp < 4; ++mp) {
        const int m_even = ty * 8 + mp * 2;
#pragma unroll
        for (int par = 0; par < 2; ++par) {
            const int r = m0 + m_even + par;
            const int t = r & 4095, b = r >> 12;
            float4 v;
            v.x = par ? u2f(acc[mp][0]).y : u2f(acc[mp][0]).x;
            v.y = par ? u2f(acc[mp][1]).y : u2f(acc[mp][1]).x;
            v.z = par ? u2f(acc[mp][2]).y : u2f(acc[mp][2]).x;
            v.w = par ? u2f(acc[mp][3]).y : u2f(acc[mp][3]).x;
            *(float4*)(gXp + (size_t)(t * TB + b) * TDD + n0 + tx * 4) = v;
        }
    }
}

// ======================= sequential recurrence kernel ======================
__global__ void __launch_bounds__(NTHR, 1)
sys2_kernel(const float* __restrict__ W1,
            const float* __restrict__ b1,
            const float* __restrict__ W2,
            const float* __restrict__ b2,
            float* __restrict__ y)
{
    __shared__ float sW1m[CJ * TD];          // W1 mem-half slice  (16 KB)
    __shared__ float sW2[CI * TDD];          // W2 slice           (16 KB)
    __shared__ float sPart[NWARP * 64];      // partials           (4 KB)
    __shared__ float sB1[CJ];
    __shared__ float sB2[CI];

    const int cta  = blockIdx.x;
    const int tid  = threadIdx.x;
    const int w    = tid >> 5;
    const int lane = tid & 31;
    const int b    = lane >> 2;
    const int kq   = lane & 3;
    const int jbase = cta * CJ;
    const int ibase = cta * CI;

    // stage weights once
    {
        float4* s1 = (float4*)sW1m;
        for (int idx = tid; idx < CJ * TD / 4; idx += NTHR) {
            const int j = idx >> 7, kf = idx & 127;
            s1[idx] = *(const float4*)(W1 + (size_t)(jbase + j) * TDD + TD + kf * 4);
        }
        float4* s2 = (float4*)sW2;
        for (int idx = tid; idx < CI * TDD / 4; idx += NTHR) {
            const int i = idx >> 8, kf = idx & 255;
            s2[idx] = *(const float4*)(W2 + (size_t)(ibase + i) * TDD + kf * 4);
        }
        if (tid < CJ) sB1[tid] = b1[jbase + tid];
        if (tid < CI) sB2[tid] = b2[ibase + tid];
    }
    __syncthreads();

    float memReg = 0.0f;   // warp0 lane l owns output o=l: bb=l>>2, ii=l&3

    for (int t = 0; t < TT; ++t) {
        // ---- prefetch xq for this step's h-epilogue (warp0, 2 per lane) ----
        float xq0 = 0.0f, xq1 = 0.0f;
        if (w == 0) {
            const int o0 = lane, o1 = lane + 32;
            xq0 = __ldg(&gXp[(size_t)(t * TB + (o0 >> 3)) * TDD + jbase + (o0 & 7)]);
            xq1 = __ldg(&gXp[(size_t)(t * TB + (o1 >> 3)) * TDD + jbase + (o1 & 7)]);
        }
        // ---- wait: mem(t-1) ready (spinner = warp 15 lane 0) ----
        if (t > 0 && tid == 480) bar_spin(&gBarM[0], (unsigned)t * NCTA);
        __syncthreads();                                  // S1

        // ===== GEMM1 (mem half only): k' in [0,512) =====
        const int kb1 = (w << 5) + (kq << 3);             // warp covers 32 k'
        ulonglong2 em0 = ldg128_cg(gMem + b * TD + kb1);
        ulonglong2 em1 = ldg128_cg(gMem + b * TD + kb1 + 4);

        unsigned long long ax[CJ], ay[CJ];
#pragma unroll
        for (int j = 0; j < CJ; ++j) { ax[j] = 0ull; ay[j] = 0ull; }
#pragma unroll
        for (int j = 0; j < CJ; ++j) {
            const ulonglong2 wv0 = *(const ulonglong2*)(sW1m + j * TD + kb1);
            const ulonglong2 wv1 = *(const ulonglong2*)(sW1m + j * TD + kb1 + 4);
            fma2(ax[j], wv0.x, em0.x); fma2(ay[j], wv0.y, em0.y);
            fma2(ax[j], wv1.x, em1.x); fma2(ay[j], wv1.y, em1.y);
        }
#pragma unroll
        for (int j = 0; j < CJ; ++j) {
            const float2 fx = u2f(ax[j]);
            const float2 fy = u2f(ay[j]);
            float s = (fx.x + fx.y) + (fy.x + fy.y);
            s += __shfl_xor_sync(0xffffffffu, s, 1);
            s += __shfl_xor_sync(0xffffffffu, s, 2);
            if (kq == 0) sPart[(w << 6) + (b << 3) + j] = s;
        }
        __syncthreads();                                  // S2

        // h-epilogue: warp 0 only (overlaps warp15's next spin)
        if (w == 0) {
#pragma unroll
            for (int half = 0; half < 2; ++half) {
                const int o = lane + half * 32;
                const int bb = o >> 3, jj = o & 7;
                float s = sB1[jj] + (half ? xq1 : xq0);
#pragma unroll
                for (int ww = 0; ww < NWARP; ++ww) s += sPart[(ww << 6) + o];
                const float hval = 0.5f * s * (1.0f + erff(s * 0.70710678118654752f));
                stg_cg(&gH[bb * TDD + jbase + jj], hval);
            }
            __syncwarp();
            if (lane == 0) bar_arrive(&gBarH[0]);
        }
        if (tid == 480) bar_spin(&gBarH[0], (unsigned)(t + 1) * NCTA);
        __syncthreads();                                  // S3

        // ===== GEMM2: p = W2 @ h, k in [0,1024) =====
        const int kb2 = (w << 6) + (kq << 4);             // warp covers 64 k
        const float* hrow = gH + b * TDD + kb2;
        ulonglong2 eh0 = ldg128_cg(hrow);
        ulonglong2 eh1 = ldg128_cg(hrow + 4);
        ulonglong2 eh2 = ldg128_cg(hrow + 8);
        ulonglong2 eh3 = ldg128_cg(hrow + 12);

        unsigned long long px[CI], py[CI];
#pragma unroll
        for (int i = 0; i < CI; ++i) { px[i] = 0ull; py[i] = 0ull; }
#pragma unroll
        for (int i = 0; i < CI; ++i) {
            const float* wr = sW2 + i * TDD + kb2;
            const ulonglong2 wv0 = *(const ulonglong2*)(wr);
            const ulonglong2 wv1 = *(const ulonglong2*)(wr + 4);
            const ulonglong2 wv2 = *(const ulonglong2*)(wr + 8);
            const ulonglong2 wv3 = *(const ulonglong2*)(wr + 12);
            fma2(px[i], wv0.x, eh0.x); fma2(py[i], wv0.y, eh0.y);
            fma2(px[i], wv1.x, eh1.x); fma2(py[i], wv1.y, eh1.y);
            fma2(px[i], wv2.x, eh2.x); fma2(py[i], wv2.y, eh2.y);
            fma2(px[i], wv3.x, eh3.x); fma2(py[i], wv3.y, eh3.y);
        }
#pragma unroll
        for (int i = 0; i < CI; ++i) {
            const float2 fx = u2f(px[i]);
            const float2 fy = u2f(py[i]);
            float s = (fx.x + fx.y) + (fy.x + fy.y);
            s += __shfl_xor_sync(0xffffffffu, s, 1);
            s += __shfl_xor_sync(0xffffffffu, s, 2);
            if (kq == 0) sPart[(w << 5) + (b << 2) + i] = s;
        }
        __syncthreads();                                  // S4

        // mem-epilogue: warp 0 lanes (o = lane) — overlaps others' next spin
        if (w == 0 && lane < TB * CI) {
            const int bb = lane >> 2, ii = lane & 3;
            float p = sB2[ii];
#pragma unroll
            for (int ww = 0; ww < NWARP; ++ww) p += sPart[(ww << 5) + lane];
            const float g = 1.0f / (1.0f + expf(-p));
            memReg = fmaf(p - memReg, g, memReg);
            stg_cg(&gMem[bb * TD + ibase + ii], memReg);
            y[((size_t)bb * TT + t) * TD + ibase + ii] = memReg;
        }
        if (w == 0) {
            __syncwarp();
            if (lane == 0) bar_arrive(&gBarM[0]);
        }
    }
}

extern "C" void kernel_launch(void* const* d_in, const int* in_sizes, int n_in,
                              void* d_out, int out_size) {
    const float* x  = (const float*)d_in[0];
    const float* W1 = (const float*)d_in[1];
    const float* b1 = (const float*)d_in[2];
    const float* W2 = (const float*)d_in[3];
    const float* b2 = (const float*)d_in[4];
    float* y = (float*)d_out;

    init_scratch<<<(TB * TD + 255) / 256, 256>>>();
    xproj_kernel<<<dim3(TDD / PN, (TB * TT) / PM), 256>>>(x, W1);
    sys2_kernel<<<NCTA, NTHR>>>(W1, b1, W2, b2, y);
}

// round 6
// speedup vs baseline: 1.2817x; 1.2817x over previous
#include <cuda_runtime.h>
#include <math.h>

#define TB   8
#define TD   512
#define TDD  1024
#define TT   4096
#define NCTA 128
#define CJ   8        // h cols per CTA
#define CI   4        // p cols per CTA
#define NTHR 256
#define NWARP 8

__device__ float gMem[TB * TD];    // recurrent state (in place; schedule-proven safe)
__device__ float gH[TB * TDD];     // hidden activations (in place)
__device__ __align__(256) unsigned gBarH[64];   // arrivals after h(t) published
__device__ __align__(256) unsigned gBarM[64];   // arrivals after mem(t) published

__global__ void init_scratch() {
    int t = blockIdx.x * blockDim.x + threadIdx.x;
    if (t < TB * TD) gMem[t] = 0.0f;
    if (t < 64) { gBarH[t] = 0u; gBarM[t] = 0u; }
}

__device__ __forceinline__ void fma2(unsigned long long& acc,
                                     unsigned long long a,
                                     unsigned long long b) {
    asm volatile("fma.rn.f32x2 %0, %1, %2, %0;" : "+l"(acc) : "l"(a), "l"(b));
}
__device__ __forceinline__ float2 u2f(unsigned long long v) {
    float2 f;
    asm("mov.b64 {%0,%1}, %2;" : "=f"(f.x), "=f"(f.y) : "l"(v));
    return f;
}
__device__ __forceinline__ ulonglong2 ldg128_cg(const void* p) {
    ulonglong2 v;
    asm volatile("ld.global.cg.v2.u64 {%0,%1}, [%2];"
                 : "=l"(v.x), "=l"(v.y) : "l"(p));
    return v;
}
__device__ __forceinline__ ulonglong2 ldg128_nc(const void* p) {
    ulonglong2 v;
    asm volatile("ld.global.nc.v2.u64 {%0,%1}, [%2];"
                 : "=l"(v.x), "=l"(v.y) : "l"(p));
    return v;
}
__device__ __forceinline__ void stg_cg(float* p, float v) {
    asm volatile("st.global.cg.f32 [%0], %1;" :: "l"(p), "f"(v) : "memory");
}
// cumulative-release arrive (after __syncwarp: publishes the epilogue warp's stores)
__device__ __forceinline__ void bar_arrive(unsigned* ctr) {
    unsigned one = 1u;
    asm volatile("red.release.gpu.global.add.u32 [%0], %1;"
                 :: "l"(ctr), "r"(one) : "memory");
}
// single-word spin, ONE thread per CTA
__device__ __forceinline__ void bar_spin(const unsigned* ctr, unsigned tgt) {
    unsigned v;
    do {
        asm volatile("ld.relaxed.gpu.global.u32 %0, [%1];"
                     : "=r"(v) : "l"(ctr) : "memory");
    } while (v < tgt);
}

__global__ void __launch_bounds__(NTHR, 1)
sys2_kernel(const float* __restrict__ x,
            const float* __restrict__ W1,
            const float* __restrict__ b1,
            const float* __restrict__ W2,
            const float* __restrict__ b2,
            float* __restrict__ y)
{
    extern __shared__ float smem[];
    float* sW1   = smem;                     // CJ*TDD (32 KB)
    float* sW2   = sW1 + CJ * TDD;           // CI*TDD (16 KB)
    float* sPart = sW2 + CI * TDD;           // NWARP*64 = 512
    float* sB1   = sPart + NWARP * 64;       // CJ
    float* sB2   = sB1 + CJ;                 // CI

    const int cta  = blockIdx.x;
    const int tid  = threadIdx.x;
    const int w    = tid >> 5;
    const int lane = tid & 31;
    const int b    = lane >> 2;
    const int kq   = lane & 3;
    const int jbase = cta * CJ;
    const int ibase = cta * CI;

    {
        const float4* g1 = (const float4*)(W1 + (size_t)jbase * TDD);
        float4* s1 = (float4*)sW1;
        for (int idx = tid; idx < CJ * TDD / 4; idx += NTHR) s1[idx] = g1[idx];
        const float4* g2 = (const float4*)(W2 + (size_t)ibase * TDD);
        float4* s2 = (float4*)sW2;
        for (int idx = tid; idx < CI * TDD / 4; idx += NTHR) s2[idx] = g2[idx];
        if (tid < CJ) sB1[tid] = b1[jbase + tid];
        if (tid < CI) sB2[tid] = b2[ibase + tid];
    }
    __syncthreads();

    float memReg = 0.0f;   // warp0 lane l owns output (bb=l>>2, ii=l&3)

    ulonglong2 ex[4];
    {
        const float* xr = x + ((size_t)b * TT) * TD;
#pragma unroll
        for (int it = 0; it < 4; ++it)
            ex[it] = ldg128_nc(xr + (w << 6) + (it << 4) + (kq << 2));
    }

    for (int t = 0; t < TT; ++t) {
        // ===== Phase 1: h = gelu(W1 @ [x_t ; mem] + b1), j-slice =====
        unsigned long long ax[CJ], ay[CJ];
#pragma unroll
        for (int j = 0; j < CJ; ++j) { ax[j] = 0ull; ay[j] = 0ull; }

        // x-half part A (independent of mem) — overlaps the spin below
#pragma unroll
        for (int it = 0; it < 2; ++it) {
            const int k = (w << 6) + (it << 4) + (kq << 2);
#pragma unroll
            for (int j = 0; j < CJ; ++j) {
                const ulonglong2 wv = *(const ulonglong2*)(sW1 + j * TDD + k);
                fma2(ax[j], wv.x, ex[it].x);
                fma2(ay[j], wv.y, ex[it].y);
            }
        }

        if (t > 0 && tid == 224) bar_spin(&gBarM[0], (unsigned)t * NCTA);
        __syncthreads();                       // S1: mem(t-1) visible chip-wide

        // mem loads in flight under x-half part B
        const float* mrow = gMem + b * TD;
        ulonglong2 em[4];
#pragma unroll
        for (int it = 0; it < 4; ++it)
            em[it] = ldg128_cg(mrow + (w << 6) + (it << 4) + (kq << 2));

#pragma unroll
        for (int it = 2; it < 4; ++it) {
            const int k = (w << 6) + (it << 4) + (kq << 2);
#pragma unroll
            for (int j = 0; j < CJ; ++j) {
                const ulonglong2 wv = *(const ulonglong2*)(sW1 + j * TDD + k);
                fma2(ax[j], wv.x, ex[it].x);
                fma2(ay[j], wv.y, ex[it].y);
            }
        }
#pragma unroll
        for (int it = 0; it < 4; ++it) {
            const int k = (w << 6) + (it << 4) + (kq << 2);
#pragma unroll
            for (int j = 0; j < CJ; ++j) {
                const ulonglong2 wv = *(const ulonglong2*)(sW1 + j * TDD + TD + k);
                fma2(ax[j], wv.x, em[it].x);
                fma2(ay[j], wv.y, em[it].y);
            }
        }
#pragma unroll
        for (int j = 0; j < CJ; ++j) {
            const float2 fx = u2f(ax[j]);
            const float2 fy = u2f(ay[j]);
            float s = (fx.x + fx.y) + (fy.x + fy.y);
            s += __shfl_xor_sync(0xffffffffu, s, 1);
            s += __shfl_xor_sync(0xffffffffu, s, 2);
            if (kq == 0) sPart[(w << 6) + (b << 3) + j] = s;
        }
        __syncthreads();                       // S2

        // h-epilogue: warp 0 only; spinner (warp 7) polls concurrently
        if (w == 0) {
#pragma unroll
            for (int half = 0; half < 2; ++half) {
                const int o = lane + (half << 5);
                const int bb = o >> 3, jj = o & 7;
                float s = sB1[jj];
#pragma unroll
                for (int ww = 0; ww < NWARP; ++ww) s += sPart[(ww << 6) + o];
                const float hval = 0.5f * s * (1.0f + erff(s * 0.70710678118654752f));
                stg_cg(&gH[bb * TDD + jbase + jj], hval);
            }
            __syncwarp();
            if (lane == 0) bar_arrive(&gBarH[0]);
        }
        if (tid == 224) bar_spin(&gBarH[0], (unsigned)(t + 1) * NCTA);
        __syncthreads();                       // S3: h(t) visible chip-wide

        // ===== Phase 2: p = W2 @ h + b2 ; gated mem update, i-slice =====
        const float* hrow = gH + b * TDD;
        ulonglong2 eh[8];
#pragma unroll
        for (int it = 0; it < 8; ++it)
            eh[it] = ldg128_cg(hrow + (w << 7) + (it << 4) + (kq << 2));

        // prefetch x(t+1) under the eh L2 latency
        {
            const int tn = (t + 1 < TT) ? (t + 1) : t;
            const float* xr = x + ((size_t)b * TT + tn) * TD;
#pragma unroll
            for (int it = 0; it < 4; ++it)
                ex[it] = ldg128_nc(xr + (w << 6) + (it << 4) + (kq << 2));
        }

        unsigned long long px[CI], py[CI];
#pragma unroll
        for (int i = 0; i < CI; ++i) { px[i] = 0ull; py[i] = 0ull; }
#pragma unroll
        for (int it = 0; it < 8; ++it) {
            const int k = (w << 7) + (it << 4) + (kq << 2);
#pragma unroll
            for (int i = 0; i < CI; ++i) {
                const ulonglong2 wv = *(const ulonglong2*)(sW2 + i * TDD + k);
                fma2(px[i], wv.x, eh[it].x);
                fma2(py[i], wv.y, eh[it].y);
            }
        }
#pragma unroll
        for (int i = 0; i < CI; ++i) {
            const float2 fx = u2f(px[i]);
            const float2 fy = u2f(py[i]);
            float s = (fx.x + fx.y) + (fy.x + fy.y);
            s += __shfl_xor_sync(0xffffffffu, s, 1);
            s += __shfl_xor_sync(0xffffffffu, s, 2);
            if (kq == 0) sPart[(w << 5) + (b << 2) + i] = s;
        }
        __syncthreads();                       // S4

        // mem-epilogue: warp 0 only; loop-top spinner overlaps it next iter
        if (w == 0) {
            const int bb = lane >> 2, ii = lane & 3;
            float p = sB2[ii];
#pragma unroll
            for (int ww = 0; ww < NWARP; ++ww) p += sPart[(ww << 5) + lane];
            const float g = 1.0f / (1.0f + expf(-p));
            memReg = fmaf(p - memReg, g, memReg);
            stg_cg(&gMem[bb * TD + ibase + ii], memReg);
            y[((size_t)bb * TT + t) * TD + ibase + ii] = memReg;
            __syncwarp();
            if (lane == 0) bar_arrive(&gBarM[0]);
        }
    }
}

extern "C" void kernel_launch(void* const* d_in, const int* in_sizes, int n_in,
                              void* d_out, int out_size) {
    const float* x  = (const float*)d_in[0];
    const float* W1 = (const float*)d_in[1];
    const float* b1 = (const float*)d_in[2];
    const float* W2 = (const float*)d_in[3];
    const float* b2 = (const float*)d_in[4];
    float* y = (float*)d_out;

    const size_t SMEM_BYTES =
        (CJ * TDD + CI * TDD + NWARP * 64 + CJ + CI) * sizeof(float);
    cudaFuncSetAttribute(sys2_kernel,
                         cudaFuncAttributeMaxDynamicSharedMemorySize,
                         (int)SMEM_BYTES);

    init_scratch<<<(TB * TD + 255) / 256, 256>>>();
    sys2_kernel<<<NCTA, NTHR, SMEM_BYTES>>>(x, W1, b1, W2, b2, y);
}

// round 7
// speedup vs baseline: 1.3110x; 1.0228x over previous
#include <cuda_runtime.h>
#include <math.h>

#define TB   8
#define TD   512
#define TDD  1024
#define TT   4096
#define NCTA 128
#define CJ   8        // h cols per CTA
#define CI   4        // p cols per CTA
#define NTHR 256
#define NWARP 8
#define NGRP 8        // barrier fan-in groups (16 CTAs each)
#define GSZ  16

__device__ float gMem[TB * TD];    // recurrent state (in place; schedule-proven safe)
__device__ float gH[TB * TDD];     // hidden activations (in place)
// 8 counters per barrier, each on its own 256B line
__device__ __align__(256) unsigned gBarH[NGRP][64];
__device__ __align__(256) unsigned gBarM[NGRP][64];

__global__ void init_scratch() {
    int t = blockIdx.x * blockDim.x + threadIdx.x;
    if (t < TB * TD) gMem[t] = 0.0f;
    if (t < NGRP * 64) {
        ((unsigned*)gBarH)[t] = 0u;
        ((unsigned*)gBarM)[t] = 0u;
    }
}

__device__ __forceinline__ void fma2(unsigned long long& acc,
                                     unsigned long long a,
                                     unsigned long long b) {
    asm volatile("fma.rn.f32x2 %0, %1, %2, %0;" : "+l"(acc) : "l"(a), "l"(b));
}
__device__ __forceinline__ float2 u2f(unsigned long long v) {
    float2 f;
    asm("mov.b64 {%0,%1}, %2;" : "=f"(f.x), "=f"(f.y) : "l"(v));
    return f;
}
__device__ __forceinline__ ulonglong2 ldg128_cg(const void* p) {
    ulonglong2 v;
    asm volatile("ld.global.cg.v2.u64 {%0,%1}, [%2];"
                 : "=l"(v.x), "=l"(v.y) : "l"(p));
    return v;
}
__device__ __forceinline__ ulonglong2 ldg128_nc(const void* p) {
    ulonglong2 v;
    asm volatile("ld.global.nc.v2.u64 {%0,%1}, [%2];"
                 : "=l"(v.x), "=l"(v.y) : "l"(p));
    return v;
}
__device__ __forceinline__ void stg_cg(float* p, float v) {
    asm volatile("st.global.cg.f32 [%0], %1;" :: "l"(p), "f"(v) : "memory");
}
// cumulative-release arrive (after __syncthreads: publishes the CTA's prior stores)
__device__ __forceinline__ void bar_arrive(unsigned* ctr) {
    unsigned one = 1u;
    asm volatile("red.release.gpu.global.add.u32 [%0], %1;"
                 :: "l"(ctr), "r"(one) : "memory");
}
__device__ __forceinline__ unsigned ldrelax(const unsigned* p) {
    unsigned v;
    asm volatile("ld.relaxed.gpu.global.u32 %0, [%1];"
                 : "=r"(v) : "l"(p) : "memory");
    return v;
}
// poll one batch of 8 counters (8 independent L2 loads in flight)
__device__ __forceinline__ void poll8(unsigned v[NGRP], const unsigned (*ctr)[64]) {
#pragma unroll
    for (int g = 0; g < NGRP; ++g) v[g] = ldrelax(&ctr[g][0]);
}
__device__ __forceinline__ bool chk8(const unsigned v[NGRP], unsigned tgt) {
    bool ok = true;
#pragma unroll
    for (int g = 0; g < NGRP; ++g) ok &= (v[g] >= tgt);
    return ok;
}
// software-pipelined spin: two interleaved 8-load batches halve detect quantization
__device__ __forceinline__ void bar_spin8(const unsigned (*ctr)[64], unsigned tgt) {
    unsigned a[NGRP], b[NGRP];
    poll8(a, ctr);
    for (;;) {
        poll8(b, ctr);
        if (chk8(a, tgt)) break;
        poll8(a, ctr);
        if (chk8(b, tgt)) break;
    }
}

__global__ void __launch_bounds__(NTHR, 1)
sys2_kernel(const float* __restrict__ x,
            const float* __restrict__ W1,
            const float* __restrict__ b1,
            const float* __restrict__ W2,
            const float* __restrict__ b2,
            float* __restrict__ y)
{
    extern __shared__ float smem[];
    float* sW1   = smem;                     // CJ*TDD (32 KB)
    float* sW2   = sW1 + CJ * TDD;           // CI*TDD (16 KB)
    float* sPart = sW2 + CI * TDD;           // NWARP*64 = 512
    float* sB1   = sPart + NWARP * 64;       // CJ
    float* sB2   = sB1 + CJ;                 // CI

    const int cta  = blockIdx.x;
    const int tid  = threadIdx.x;
    const int w    = tid >> 5;
    const int lane = tid & 31;
    const int b    = lane >> 2;
    const int kq   = lane & 3;
    const int jbase = cta * CJ;
    const int ibase = cta * CI;
    const int grp   = cta >> 4;              // 16 CTAs per arrive-counter

    {
        const float4* g1 = (const float4*)(W1 + (size_t)jbase * TDD);
        float4* s1 = (float4*)sW1;
        for (int idx = tid; idx < CJ * TDD / 4; idx += NTHR) s1[idx] = g1[idx];
        const float4* g2 = (const float4*)(W2 + (size_t)ibase * TDD);
        float4* s2 = (float4*)sW2;
        for (int idx = tid; idx < CI * TDD / 4; idx += NTHR) s2[idx] = g2[idx];
        if (tid < CJ) sB1[tid] = b1[jbase + tid];
        if (tid < CI) sB2[tid] = b2[ibase + tid];
    }
    __syncthreads();

    float memReg = 0.0f;   // tid<32 owns output (bb=tid>>2, ii=tid&3)

    ulonglong2 ex[4];
    {
        const float* xr = x + ((size_t)b * TT) * TD;
#pragma unroll
        for (int it = 0; it < 4; ++it)
            ex[it] = ldg128_nc(xr + (w << 6) + (it << 4) + (kq << 2));
    }

    for (int t = 0; t < TT; ++t) {
        // ===== Phase 1: h = gelu(W1 @ [x_t ; mem] + b1), j-slice =====
        unsigned long long ax[CJ], ay[CJ];
#pragma unroll
        for (int j = 0; j < CJ; ++j) { ax[j] = 0ull; ay[j] = 0ull; }

        // x-half part A (independent of mem) — overlaps the spin below
#pragma unroll
        for (int it = 0; it < 2; ++it) {
            const int k = (w << 6) + (it << 4) + (kq << 2);
#pragma unroll
            for (int j = 0; j < CJ; ++j) {
                const ulonglong2 wv = *(const ulonglong2*)(sW1 + j * TDD + k);
                fma2(ax[j], wv.x, ex[it].x);
                fma2(ay[j], wv.y, ex[it].y);
            }
        }

        if (t > 0 && tid == 0) bar_spin8(gBarM, (unsigned)t * GSZ);
        __syncthreads();                       // S1: mem(t-1) visible chip-wide

        // mem loads in flight under x-half part B
        const float* mrow = gMem + b * TD;
        ulonglong2 em[4];
#pragma unroll
        for (int it = 0; it < 4; ++it)
            em[it] = ldg128_cg(mrow + (w << 6) + (it << 4) + (kq << 2));

#pragma unroll
        for (int it = 2; it < 4; ++it) {
            const int k = (w << 6) + (it << 4) + (kq << 2);
#pragma unroll
            for (int j = 0; j < CJ; ++j) {
                const ulonglong2 wv = *(const ulonglong2*)(sW1 + j * TDD + k);
                fma2(ax[j], wv.x, ex[it].x);
                fma2(ay[j], wv.y, ex[it].y);
            }
        }
#pragma unroll
        for (int it = 0; it < 4; ++it) {
            const int k = (w << 6) + (it << 4) + (kq << 2);
#pragma unroll
            for (int j = 0; j < CJ; ++j) {
                const ulonglong2 wv = *(const ulonglong2*)(sW1 + j * TDD + TD + k);
                fma2(ax[j], wv.x, em[it].x);
                fma2(ay[j], wv.y, em[it].y);
            }
        }
#pragma unroll
        for (int j = 0; j < CJ; ++j) {
            const float2 fx = u2f(ax[j]);
            const float2 fy = u2f(ay[j]);
            float s = (fx.x + fx.y) + (fy.x + fy.y);
            s += __shfl_xor_sync(0xffffffffu, s, 1);
            s += __shfl_xor_sync(0xffffffffu, s, 2);
            if (kq == 0) sPart[(w << 6) + (b << 3) + j] = s;
        }
        __syncthreads();                       // S2

        // h-epilogue: threads 0..63 (warps 0-1), 1 output each
        if (tid < TB * CJ) {
            const int bb = tid >> 3, jj = tid & 7;
            float s = sB1[jj];
#pragma unroll
            for (int ww = 0; ww < NWARP; ++ww) s += sPart[(ww << 6) + tid];
            const float hval = 0.5f * s * (1.0f + erff(s * 0.70710678118654752f));
            stg_cg(&gH[bb * TDD + jbase + jj], hval);
        }
        __syncthreads();                       // S2b: h stores done CTA-wide
        if (tid == 0) bar_arrive(&gBarH[grp][0]);

        // prefetch x(t+1) — overlaps the h-barrier wait
        {
            const int tn = (t + 1 < TT) ? (t + 1) : t;
            const float* xr = x + ((size_t)b * TT + tn) * TD;
#pragma unroll
            for (int it = 0; it < 4; ++it)
                ex[it] = ldg128_nc(xr + (w << 6) + (it << 4) + (kq << 2));
        }

        if (tid == 0) bar_spin8(gBarH, (unsigned)(t + 1) * GSZ);
        __syncthreads();                       // S3: h(t) visible chip-wide

        // ===== Phase 2: p = W2 @ h + b2 ; gated mem update, i-slice =====
        const float* hrow = gH + b * TDD;
        ulonglong2 eh[8];
#pragma unroll
        for (int it = 0; it < 8; ++it)
            eh[it] = ldg128_cg(hrow + (w << 7) + (it << 4) + (kq << 2));

        unsigned long long px[CI], py[CI];
#pragma unroll
        for (int i = 0; i < CI; ++i) { px[i] = 0ull; py[i] = 0ull; }
#pragma unroll
        for (int it = 0; it < 8; ++it) {
            const int k = (w << 7) + (it << 4) + (kq << 2);
#pragma unroll
            for (int i = 0; i < CI; ++i) {
                const ulonglong2 wv = *(const ulonglong2*)(sW2 + i * TDD + k);
                fma2(px[i], wv.x, eh[it].x);
                fma2(py[i], wv.y, eh[it].y);
            }
        }
#pragma unroll
        for (int i = 0; i < CI; ++i) {
            const float2 fx = u2f(px[i]);
            const float2 fy = u2f(py[i]);
            float s = (fx.x + fx.y) + (fy.x + fy.y);
            s += __shfl_xor_sync(0xffffffffu, s, 1);
            s += __shfl_xor_sync(0xffffffffu, s, 2);
            if (kq == 0) sPart[(w << 5) + (b << 2) + i] = s;
        }
        __syncthreads();                       // S4

        // mem-epilogue: threads 0..31, 1 output each
        float pv = 0.0f, gv = 0.0f;
        if (tid < TB * CI) {
            const int bb = tid >> 2, ii = tid & 3;
            float p = sB2[ii];
#pragma unroll
            for (int ww = 0; ww < NWARP; ++ww) p += sPart[(ww << 5) + tid];
            const float g = 1.0f / (1.0f + expf(-p));
            memReg = fmaf(p - memReg, g, memReg);
            stg_cg(&gMem[bb * TD + ibase + ii], memReg);
        }
        __syncthreads();                       // S4b: mem stores done CTA-wide
        if (tid == 0) bar_arrive(&gBarM[grp][0]);
        // y store off the release critical path
        if (tid < TB * CI) {
            const int bb = tid >> 2, ii = tid & 3;
            y[((size_t)bb * TT + t) * TD + ibase + ii] = memReg;
        }
        (void)pv; (void)gv;
    }
}

extern "C" void kernel_launch(void* const* d_in, const int* in_sizes, int n_in,
                              void* d_out, int out_size) {
    const float* x  = (const float*)d_in[0];
    const float* W1 = (const float*)d_in[1];
    const float* b1 = (const float*)d_in[2];
    const float* W2 = (const float*)d_in[3];
    const float* b2 = (const float*)d_in[4];
    float* y = (float*)d_out;

    const size_t SMEM_BYTES =
        (CJ * TDD + CI * TDD + NWARP * 64 + CJ + CI) * sizeof(float);
    cudaFuncSetAttribute(sys2_kernel,
                         cudaFuncAttributeMaxDynamicSharedMemorySize,
                         (int)SMEM_BYTES);

    init_scratch<<<(TB * TD + 255) / 256, 256>>>();
    sys2_kernel<<<NCTA, NTHR, SMEM_BYTES>>>(x, W1, b1, W2, b2, y);
}